// round 8
// baseline (speedup 1.0000x reference)
#include <cuda_runtime.h>

#define FLTMAX 3.402823466e+38f

// ---------------- device scratch ----------------
__device__ float g_y1[32768 * 32];      // conv1 output [B*N, 32]
__device__ float g_feats[32768 * 64];   // conv2 output [B*N, 64]
__device__ float g_p1[128 * 64];        // mlp1 item partials [128][sum32|sq32]
__device__ float g_p2[256 * 128];       // mlp3 block partials [256][sum64|sq64]
__device__ int   g_fps[16384];          // [B, 2048]
__device__ float g_pooled[16384 * 68];  // [B*S][feat64 | xyz3 | pad]
__device__ float g_y3[16384 * 64];      // conv3 output [B*S, 64]

// ---------------- control state (re-zeroed each launch by init kernel) ----
__device__ int g_q;            // work-queue head
__device__ int g_done1;        // mlp1 items finished (target 128)
__device__ int g_done2;        // mlp2 items finished (target 256)
__device__ int g_smid_ready;   // how many FPS CTAs published their smid (target 4)
__device__ int g_prog[8];      // FPS progress per batch (# indices written)
__device__ int g_fps_sm[4];    // smid of each FPS CTA

__global__ void init_kernel() {
    int t = threadIdx.x;
    if (t == 0) { g_q = 0; g_done1 = 0; g_done2 = 0; g_smid_ready = 0; }
    if (t < 8) g_prog[t] = 0;
}

// ---------------- packed f32x2 helpers (per-lane .rn == scalar .rn) ----------------
__device__ __forceinline__ unsigned long long f2_add(unsigned long long a, unsigned long long b) {
    unsigned long long r;
    asm("add.rn.f32x2 %0, %1, %2;" : "=l"(r) : "l"(a), "l"(b));
    return r;
}
__device__ __forceinline__ unsigned long long f2_mul(unsigned long long a, unsigned long long b) {
    unsigned long long r;
    asm("mul.rn.f32x2 %0, %1, %2;" : "=l"(r) : "l"(a), "l"(b));
    return r;
}
__device__ __forceinline__ unsigned long long f2_pack(float lo, float hi) {
    unsigned long long r;
    asm("mov.b64 %0, {%1, %2};" : "=l"(r) : "f"(lo), "f"(hi));
    return r;
}
__device__ __forceinline__ float2 f2_unpack(unsigned long long v) {
    float2 f;
    asm("mov.b64 {%0, %1}, %2;" : "=f"(f.x), "=f"(f.y) : "l"(v));
    return f;
}

// =================================================================
// MEGA KERNEL: FPS (CTAs 0-3, 2 batches each) + work-queue workers
// queue: [0,128) mlp1 (256 pts) -> [128,384) mlp2 (128 pts)
//        -> [384,640) knn (64 queries)
// dynamic smem = 98304 (FPS: 2 x 48KB point tiles; workers use < 54KB)
// =================================================================
__global__ void __launch_bounds__(256)
mega_kernel(const float* __restrict__ x,
            const float* __restrict__ W1, const float* __restrict__ b1,
            const float* __restrict__ W2, const float* __restrict__ b2,
            const float* __restrict__ g1, const float* __restrict__ be1) {
    extern __shared__ char smraw[];
    int tid = threadIdx.x;

    if (blockIdx.x < 4) {
        // ============ FPS: one CTA per 2 batches, interleaved ============
        int cta = blockIdx.x;
        int b0 = 2 * cta, b1 = 2 * cta + 1;
        float* px0 = (float*)smraw;
        float* py0 = px0 + 4096;
        float* pz0 = py0 + 4096;
        float* px1 = pz0 + 4096;
        float* py1 = px1 + 4096;
        float* pz1 = py1 + 4096;
        __shared__ unsigned rv0[2][8], ri0[2][8], rv1[2][8], ri1[2][8];
        int lane = tid & 31, warp = tid >> 5;
        const float* xa = x + b0 * 12288;
        const float* xbb = x + b1 * 12288;

        if (tid == 0) {
            unsigned sm_;
            asm("mov.u32 %0, %%smid;" : "=r"(sm_));
            g_fps_sm[cta] = (int)sm_;
            __threadfence();
            atomicAdd(&g_smid_ready, 1);
        }

        // negated points in registers: dx = c + (-p); (-t)^2 == t^2 exactly
        unsigned long long NX0[8], NY0[8], NZ0[8], NX1[8], NY1[8], NZ1[8];
        float dd0[16], dd1[16];
        #pragma unroll
        for (int k = 0; k < 8; k++) {
            int i = 2 * tid + 512 * k;
            float ax0 = xa[3 * i],     ay0 = xa[3 * i + 1], az0 = xa[3 * i + 2];
            float ax1 = xa[3 * i + 3], ay1 = xa[3 * i + 4], az1 = xa[3 * i + 5];
            px0[i] = ax0; py0[i] = ay0; pz0[i] = az0;
            px0[i + 1] = ax1; py0[i + 1] = ay1; pz0[i + 1] = az1;
            NX0[k] = f2_pack(-ax0, -ax1); NY0[k] = f2_pack(-ay0, -ay1); NZ0[k] = f2_pack(-az0, -az1);
            float bx0 = xbb[3 * i],     by0 = xbb[3 * i + 1], bz0 = xbb[3 * i + 2];
            float bx1 = xbb[3 * i + 3], by1 = xbb[3 * i + 4], bz1 = xbb[3 * i + 5];
            px1[i] = bx0; py1[i] = by0; pz1[i] = bz0;
            px1[i + 1] = bx1; py1[i + 1] = by1; pz1[i + 1] = bz1;
            NX1[k] = f2_pack(-bx0, -bx1); NY1[k] = f2_pack(-by0, -by1); NZ1[k] = f2_pack(-bz0, -bz1);
            dd0[2 * k] = FLTMAX; dd0[2 * k + 1] = FLTMAX;
            dd1[2 * k] = FLTMAX; dd1[2 * k + 1] = FLTMAX;
        }
        __syncthreads();

        int far0 = 0, far1 = 0;
        int* out0 = g_fps + b0 * 2048;
        int* out1 = g_fps + b1 * 2048;

        for (int s = 0; s < 2048; s++) {
            if (tid == 0) { out0[s] = far0; out1[s] = far1; }
            int p = s & 1;
            // ---- batch 0: update + stage-1 ----
            {
                float cxs = px0[far0], cys = py0[far0], czs = pz0[far0];
                unsigned long long cx = f2_pack(cxs, cxs);
                unsigned long long cy = f2_pack(cys, cys);
                unsigned long long cz = f2_pack(czs, czs);
                #pragma unroll
                for (int k = 0; k < 8; k++) {
                    unsigned long long dx = f2_add(NX0[k], cx);
                    unsigned long long dy = f2_add(NY0[k], cy);
                    unsigned long long dz = f2_add(NZ0[k], cz);
                    unsigned long long d = f2_add(f2_add(f2_mul(dx, dx), f2_mul(dy, dy)),
                                                  f2_mul(dz, dz));
                    float2 f = f2_unpack(d);
                    dd0[2 * k]     = fminf(dd0[2 * k], f.x);
                    dd0[2 * k + 1] = fminf(dd0[2 * k + 1], f.y);
                }
                float tv[16]; int ts[16];
                #pragma unroll
                for (int i = 0; i < 16; i++) { tv[i] = dd0[i]; ts[i] = i; }
                #pragma unroll
                for (int off = 8; off; off >>= 1)
                    #pragma unroll
                    for (int i = 0; i < off; i++)
                        if (tv[i + off] > tv[i]) { tv[i] = tv[i + off]; ts[i] = ts[i + off]; }
                int slot = ts[0];
                int bi = 2 * tid + 512 * (slot >> 1) + (slot & 1);
                unsigned vb = __float_as_uint(tv[0]);
                unsigned wm = __reduce_max_sync(0xffffffffu, vb);
                unsigned cand = (vb == wm) ? (unsigned)bi : 0xffffffffu;
                unsigned wi = __reduce_min_sync(0xffffffffu, cand);
                if (lane == 0) { rv0[p][warp] = wm; ri0[p][warp] = wi; }
            }
            // ---- batch 1: update + stage-1 ----
            {
                float cxs = px1[far1], cys = py1[far1], czs = pz1[far1];
                unsigned long long cx = f2_pack(cxs, cxs);
                unsigned long long cy = f2_pack(cys, cys);
                unsigned long long cz = f2_pack(czs, czs);
                #pragma unroll
                for (int k = 0; k < 8; k++) {
                    unsigned long long dx = f2_add(NX1[k], cx);
                    unsigned long long dy = f2_add(NY1[k], cy);
                    unsigned long long dz = f2_add(NZ1[k], cz);
                    unsigned long long d = f2_add(f2_add(f2_mul(dx, dx), f2_mul(dy, dy)),
                                                  f2_mul(dz, dz));
                    float2 f = f2_unpack(d);
                    dd1[2 * k]     = fminf(dd1[2 * k], f.x);
                    dd1[2 * k + 1] = fminf(dd1[2 * k + 1], f.y);
                }
                float tv[16]; int ts[16];
                #pragma unroll
                for (int i = 0; i < 16; i++) { tv[i] = dd1[i]; ts[i] = i; }
                #pragma unroll
                for (int off = 8; off; off >>= 1)
                    #pragma unroll
                    for (int i = 0; i < off; i++)
                        if (tv[i + off] > tv[i]) { tv[i] = tv[i + off]; ts[i] = ts[i + off]; }
                int slot = ts[0];
                int bi = 2 * tid + 512 * (slot >> 1) + (slot & 1);
                unsigned vb = __float_as_uint(tv[0]);
                unsigned wm = __reduce_max_sync(0xffffffffu, vb);
                unsigned cand = (vb == wm) ? (unsigned)bi : 0xffffffffu;
                unsigned wi = __reduce_min_sync(0xffffffffu, cand);
                if (lane == 0) { rv1[p][warp] = wm; ri1[p][warp] = wi; }
            }
            __syncthreads();
            // ---- stage-2 for both batches (chains overlap) ----
            {
                unsigned v  = rv0[p][lane & 7];
                unsigned i2 = ri0[p][lane & 7];
                unsigned m2 = __reduce_max_sync(0xffffffffu, v);
                unsigned c2 = (v == m2) ? i2 : 0xffffffffu;
                far0 = (int)__reduce_min_sync(0xffffffffu, c2);
            }
            {
                unsigned v  = rv1[p][lane & 7];
                unsigned i2 = ri1[p][lane & 7];
                unsigned m2 = __reduce_max_sync(0xffffffffu, v);
                unsigned c2 = (v == m2) ? i2 : 0xffffffffu;
                far1 = (int)__reduce_min_sync(0xffffffffu, c2);
            }
            if (tid == 0 && (s & 31) == 31) {
                __threadfence();
                *(volatile int*)&g_prog[b0] = s + 1;
                *(volatile int*)&g_prog[b1] = s + 1;
            }
        }
        return;
    }

    // ======================= WORKERS =======================
    {
        unsigned mysm;
        asm("mov.u32 %0, %%smid;" : "=r"(mysm));
        while (*(volatile int*)&g_smid_ready < 4) __nanosleep(64);
        bool onfps = false;
        #pragma unroll
        for (int i = 0; i < 4; i++) onfps |= (g_fps_sm[i] == (int)mysm);
        if (onfps) return;   // keep FPS SMs uncontended
    }

    __shared__ int s_item;
    for (;;) {
        if (tid == 0) s_item = atomicAdd(&g_q, 1);
        __syncthreads();
        int it = s_item;
        __syncthreads();
        if (it >= 640) return;

        if (it < 128) {
            // ---------- mlp1 item: conv1(3->32)+BN1 partials, 256 pts ----------
            __shared__ float sW1[96], sb1[32], ssum[32], ssq[32];
            if (tid < 96) sW1[tid] = W1[tid];
            if (tid < 32) { sb1[tid] = b1[tid]; ssum[tid] = 0.0f; ssq[tid] = 0.0f; }
            __syncthreads();
            int p = it * 256 + tid;
            float X = x[3 * p], Y = x[3 * p + 1], Z = x[3 * p + 2];
            int lane = tid & 31;
            for (int c = 0; c < 32; c++) {
                float v = fmaf(sW1[3 * c + 2], Z,
                          fmaf(sW1[3 * c + 1], Y, fmaf(sW1[3 * c], X, sb1[c])));
                g_y1[p * 32 + c] = v;
                float sv = v, sq = v * v;
                #pragma unroll
                for (int off = 16; off; off >>= 1) {
                    sv += __shfl_down_sync(0xffffffffu, sv, off);
                    sq += __shfl_down_sync(0xffffffffu, sq, off);
                }
                if (lane == 0) { atomicAdd(&ssum[c], sv); atomicAdd(&ssq[c], sq); }
            }
            __syncthreads();
            if (tid < 32) {
                g_p1[it * 64 + tid] = ssum[tid];
                g_p1[it * 64 + 32 + tid] = ssq[tid];
            }
            __threadfence();
            __syncthreads();
            if (tid == 0) atomicAdd(&g_done1, 1);
        } else if (it < 384) {
            // ---------- mlp2 item: BN1+ReLU+conv2(32->64), 128 pts, transposed ----------
            int j = it - 128;                        // 0..255 -> covers all 32768 pts
            float* y1t = (float*)smraw;              // [128*32]
            float* W2s = (float*)smraw + 4096;       // [64*36] padded
            __shared__ float sc1[32], sh1[32], sb2[64];
            if (tid == 0) { while (*(volatile int*)&g_done1 < 128) __nanosleep(64); }
            __syncthreads();
            __threadfence();
            if (tid < 32) {
                float sum = 0.0f, sq = 0.0f;
                for (int k = 0; k < 128; k++) {
                    sum += g_p1[k * 64 + tid];
                    sq  += g_p1[k * 64 + 32 + tid];
                }
                float mean = sum / 32768.0f;
                float var  = sq / 32768.0f - mean * mean;
                float scl  = g1[tid] * rsqrtf(var + 1e-5f);
                sc1[tid] = scl;
                sh1[tid] = be1[tid] - mean * scl;
            }
            if (tid < 64) sb2[tid] = b2[tid];
            for (int i = tid; i < 2048; i += 256) {
                int o = i >> 5, c = i & 31;
                W2s[o * 36 + c] = W2[i];
            }
            __syncthreads();
            int p0 = j * 128;
            for (int i = tid; i < 4096; i += 256) {
                int c = i & 31;
                y1t[i] = fmaxf(fmaf(g_y1[p0 * 32 + i], sc1[c], sh1[c]), 0.0f);
            }
            __syncthreads();
            int o = tid & 63, q = tid >> 6;
            float acc[32];
            #pragma unroll
            for (int p = 0; p < 32; p++) acc[p] = sb2[o];
            const float4* wr = (const float4*)(W2s + o * 36);
            #pragma unroll
            for (int c4 = 0; c4 < 8; c4++) {
                float4 w = wr[c4];
                #pragma unroll
                for (int p = 0; p < 32; p++) {
                    float4 v = *(const float4*)(y1t + (q * 32 + p) * 32 + c4 * 4);
                    acc[p] = fmaf(w.x, v.x, fmaf(w.y, v.y,
                             fmaf(w.z, v.z, fmaf(w.w, v.w, acc[p]))));
                }
            }
            #pragma unroll
            for (int p = 0; p < 32; p++)
                g_feats[(p0 + q * 32 + p) * 64 + o] = acc[p];
            __threadfence();
            __syncthreads();
            if (tid == 0) atomicAdd(&g_done2, 1);
        } else {
            // ---------- knn item: 64 queries, 4 threads/query ----------
            int k = it - 384;
            int b = k & 7, grp = k >> 3;
            int s0 = grp * 64;
            float* sx = (float*)smraw;           // [1056]
            float* sy = sx + 1056;
            float* sz = sy + 1056;
            float* snn = sz + 1056;
            float2* mg = (float2*)(smraw + 16896);   // [64*64]
            int* klist = (int*)(smraw + 49664);      // [64*16]

            if (tid == 0) { while (*(volatile int*)&g_prog[b] < s0 + 64) __nanosleep(128); }
            __syncthreads();
            __threadfence();

            int r = tid & 3, ql = tid >> 2;
            int s = s0 + ql;
            const float* xb = x + b * 12288;
            int qi = g_fps[b * 2048 + s];
            float qx = xb[3 * qi], qy = xb[3 * qi + 1], qz = xb[3 * qi + 2];
            float qn = __fadd_rn(__fadd_rn(__fmul_rn(qx, qx), __fmul_rn(qy, qy)),
                                 __fmul_rn(qz, qz));
            unsigned long long qx2 = f2_pack(qx, qx), qy2 = f2_pack(qy, qy);
            unsigned long long qz2 = f2_pack(qz, qz);
            unsigned long long qn2 = f2_pack(qn, qn), n2 = f2_pack(-2.0f, -2.0f);

            float bd[16];
            int   bi[16];
            #pragma unroll
            for (int m = 0; m < 16; m++) { bd[m] = FLTMAX; bi[m] = 0x7fffffff; }
            float w = FLTMAX;
            int ws = 0;

            for (int t = 0; t < 4; t++) {
                __syncthreads();
                for (int jj = tid; jj < 1024; jj += 256) {
                    int i = t * 1024 + jj;
                    int slotp = (jj >> 8) * 264 + (jj & 255);
                    float X = xb[3 * i], Y = xb[3 * i + 1], Z = xb[3 * i + 2];
                    sx[slotp] = X; sy[slotp] = Y; sz[slotp] = Z;
                    snn[slotp] = __fadd_rn(__fadd_rn(__fmul_rn(X, X), __fmul_rn(Y, Y)),
                                           __fmul_rn(Z, Z));
                }
                __syncthreads();
                int qbase = r * 264;
                const float2* px2 = (const float2*)(sx + qbase);
                const float2* py2 = (const float2*)(sy + qbase);
                const float2* pz2 = (const float2*)(sz + qbase);
                const float2* pn2 = (const float2*)(snn + qbase);
                int base = t * 1024 + r * 256;
                for (int j2 = 0; j2 < 128; j2++) {
                    float2 vx = px2[j2], vy = py2[j2], vz = pz2[j2], vn = pn2[j2];
                    unsigned long long dot = f2_add(f2_add(f2_mul(qx2, f2_pack(vx.x, vx.y)),
                                                           f2_mul(qy2, f2_pack(vy.x, vy.y))),
                                                    f2_mul(qz2, f2_pack(vz.x, vz.y)));
                    unsigned long long d2 = f2_add(f2_add(qn2, f2_pack(vn.x, vn.y)),
                                                   f2_mul(dot, n2));
                    float2 d = f2_unpack(d2);
                    if (fminf(d.x, d.y) < w) {
                        #pragma unroll
                        for (int h = 0; h < 2; h++) {
                            float dv = h ? d.y : d.x;
                            if (dv < w) {
                                int i = base + 2 * j2 + h;
                                #pragma unroll
                                for (int m = 0; m < 16; m++)
                                    if (m == ws) { bd[m] = dv; bi[m] = i; }
                                float nw = -FLTMAX; int nwi = -1; int nws = 0;
                                #pragma unroll
                                for (int m = 0; m < 16; m++) {
                                    bool better = (bd[m] > nw) || (bd[m] == nw && bi[m] > nwi);
                                    if (better) { nw = bd[m]; nwi = bi[m]; nws = m; }
                                }
                                w = nw; ws = nws;
                            }
                        }
                    }
                }
            }

            // 4-way rank merge over disjoint-index union of 64 candidates
            __syncthreads();
            #pragma unroll
            for (int m = 0; m < 16; m++)
                mg[ql * 64 + r * 16 + m] = make_float2(bd[m], __int_as_float(bi[m]));
            __syncwarp();
            int rank[16];
            #pragma unroll
            for (int m = 0; m < 16; m++) rank[m] = 0;
            const float2* u = &mg[ql * 64];
            for (int e = 0; e < 64; e++) {
                float2 pe = u[e];
                int pi = __float_as_int(pe.y);
                #pragma unroll
                for (int m = 0; m < 16; m++)
                    rank[m] += (pe.x < bd[m]) || (pe.x == bd[m] && pi < bi[m]);
            }
            int* kl = &klist[ql * 16];
            #pragma unroll
            for (int m = 0; m < 16; m++)
                if (rank[m] < 16) kl[rank[m]] = bi[m];
            __syncwarp();

            int idx16[16];
            #pragma unroll
            for (int kk = 0; kk < 16; kk++) idx16[kk] = kl[kk];

            // wait for all feats before gather
            __syncthreads();
            if (tid == 0) { while (*(volatile int*)&g_done2 < 256) __nanosleep(128); }
            __syncthreads();
            __threadfence();

            float* op = g_pooled + (b * 2048 + s) * 68;
            if (r == 0) {
                float mx = -FLTMAX, my = -FLTMAX, mz = -FLTMAX;
                #pragma unroll
                for (int kk = 0; kk < 16; kk++) {
                    int i = idx16[kk];
                    mx = fmaxf(mx, __fsub_rn(xb[3 * i], qx));
                    my = fmaxf(my, __fsub_rn(xb[3 * i + 1], qy));
                    mz = fmaxf(mz, __fsub_rn(xb[3 * i + 2], qz));
                }
                op[64] = mx; op[65] = my; op[66] = mz; op[67] = 0.0f;
            }
            const float* fb = g_feats + b * 4096 * 64 + r * 16;
            float4 acc[4];
            #pragma unroll
            for (int q = 0; q < 4; q++)
                acc[q] = make_float4(-FLTMAX, -FLTMAX, -FLTMAX, -FLTMAX);
            #pragma unroll
            for (int kk = 0; kk < 16; kk++) {
                const float4* fr = (const float4*)(fb + idx16[kk] * 64);
                #pragma unroll
                for (int q = 0; q < 4; q++) {
                    float4 f = fr[q];
                    acc[q].x = fmaxf(acc[q].x, f.x);
                    acc[q].y = fmaxf(acc[q].y, f.y);
                    acc[q].z = fmaxf(acc[q].z, f.z);
                    acc[q].w = fmaxf(acc[q].w, f.w);
                }
            }
            float4* of = (float4*)(op + r * 16);
            #pragma unroll
            for (int q = 0; q < 4; q++) of[q] = acc[q];
            __syncthreads();
        }
    }
}

// ---------------- mlp3: conv3(67->64) transposed + BN2 partials ----------------
__global__ void __launch_bounds__(128) mlp3_kernel(const float* __restrict__ W3,
                                                   const float* __restrict__ b3) {
    __shared__ float P[64 * 68];
    __shared__ float W[64 * 68];
    __shared__ float sb[64];
    __shared__ float red[128];
    int tid = threadIdx.x;
    for (int i = tid; i < 64 * 68; i += 128) {
        int o = i / 68, c = i - o * 68;
        W[i] = (c < 64) ? W3[o * 67 + 3 + c] : ((c < 67) ? W3[o * 67 + (c - 64)] : 0.0f);
    }
    if (tid < 64) sb[tid] = b3[tid];
    int p0 = blockIdx.x * 64;
    for (int i = tid; i < 64 * 68; i += 128) P[i] = g_pooled[p0 * 68 + i];
    __syncthreads();
    int o = tid & 63, h = tid >> 6;
    float acc[32];
    #pragma unroll
    for (int p = 0; p < 32; p++) acc[p] = sb[o];
    const float4* wr = (const float4*)(W + o * 68);
    #pragma unroll
    for (int c4 = 0; c4 < 17; c4++) {
        float4 w = wr[c4];
        #pragma unroll
        for (int p = 0; p < 32; p++) {
            float4 v = *(const float4*)(P + (h * 32 + p) * 68 + c4 * 4);
            acc[p] = fmaf(w.x, v.x, fmaf(w.y, v.y, fmaf(w.z, v.z, fmaf(w.w, v.w, acc[p]))));
        }
    }
    float ssum = 0.0f, ssq = 0.0f;
    #pragma unroll
    for (int p = 0; p < 32; p++) {
        g_y3[(p0 + h * 32 + p) * 64 + o] = acc[p];
        ssum += acc[p]; ssq += acc[p] * acc[p];
    }
    red[tid] = ssum;
    __syncthreads();
    if (tid < 64) g_p2[blockIdx.x * 128 + tid] = red[tid] + red[tid + 64];
    __syncthreads();
    red[tid] = ssq;
    __syncthreads();
    if (tid < 64) g_p2[blockIdx.x * 128 + 64 + tid] = red[tid] + red[tid + 64];
}

// ---------------- mlp4: BN2 finalize (in-block) + ReLU + conv4 -> out ----------------
__global__ void __launch_bounds__(128) mlp4_kernel(const float* __restrict__ W4,
                                                   const float* __restrict__ b4,
                                                   const float* __restrict__ g2,
                                                   const float* __restrict__ be2,
                                                   float* __restrict__ out) {
    __shared__ float Y[64 * 64];
    __shared__ float W[64 * 68];
    __shared__ float sb[64], sc[64], sh[64];
    int tid = threadIdx.x;
    if (tid < 64) {
        sb[tid] = b4[tid];
        float sum = 0.0f, sq = 0.0f;
        for (int k = 0; k < 256; k++) {
            sum += g_p2[k * 128 + tid];
            sq  += g_p2[k * 128 + 64 + tid];
        }
        float mean = sum / 16384.0f;
        float var  = sq / 16384.0f - mean * mean;
        float scl  = g2[tid] * rsqrtf(var + 1e-5f);
        sc[tid] = scl;
        sh[tid] = be2[tid] - mean * scl;
    }
    for (int i = tid; i < 64 * 68; i += 128) {
        int o = i / 68, c = i - o * 68;
        W[i] = (c < 64) ? W4[o * 64 + c] : 0.0f;
    }
    __syncthreads();
    int p0 = blockIdx.x * 64;
    for (int i = tid; i < 4096; i += 128) {
        int c = i & 63;
        Y[i] = fmaxf(fmaf(g_y3[p0 * 64 + i], sc[c], sh[c]), 0.0f);
    }
    __syncthreads();
    int o = tid & 63, h = tid >> 6;
    float acc[32];
    #pragma unroll
    for (int p = 0; p < 32; p++) acc[p] = sb[o];
    const float4* wr = (const float4*)(W + o * 68);
    #pragma unroll
    for (int c4 = 0; c4 < 16; c4++) {
        float4 w = wr[c4];
        #pragma unroll
        for (int p = 0; p < 32; p++) {
            float4 v = *(const float4*)(Y + (h * 32 + p) * 64 + c4 * 4);
            acc[p] = fmaf(w.x, v.x, fmaf(w.y, v.y, fmaf(w.z, v.z, fmaf(w.w, v.w, acc[p]))));
        }
    }
    #pragma unroll
    for (int p = 0; p < 32; p++)
        out[(p0 + h * 32 + p) * 64 + o] = acc[p];
}

// ---------------- launch ----------------
extern "C" void kernel_launch(void* const* d_in, const int* in_sizes, int n_in,
                              void* d_out, int out_size) {
    const float* x   = (const float*)d_in[0];
    const float* W1  = (const float*)d_in[1];
    const float* b1  = (const float*)d_in[2];
    const float* g1  = (const float*)d_in[3];
    const float* be1 = (const float*)d_in[4];
    const float* W2  = (const float*)d_in[5];
    const float* b2  = (const float*)d_in[6];
    const float* W3  = (const float*)d_in[7];
    const float* b3  = (const float*)d_in[8];
    const float* g2  = (const float*)d_in[9];
    const float* be2 = (const float*)d_in[10];
    const float* W4  = (const float*)d_in[11];
    const float* b4  = (const float*)d_in[12];
    float* out = (float*)d_out;

    cudaFuncSetAttribute(mega_kernel, cudaFuncAttributeMaxDynamicSharedMemorySize, 98304);

    init_kernel<<<1, 32>>>();
    mega_kernel<<<292, 256, 98304>>>(x, W1, b1, W2, b2, g1, be1);
    mlp3_kernel<<<256, 128>>>(W3, b3);
    mlp4_kernel<<<256, 128>>>(W4, b4, g2, be2, out);
}

// round 9
// speedup vs baseline: 1.4695x; 1.4695x over previous
#include <cuda_runtime.h>

#define FLTMAX 3.402823466e+38f

// ---------------- device scratch ----------------
__device__ float g_y1[32768 * 32];      // conv1 output [B*N, 32]
__device__ float g_feats[32768 * 64];   // conv2 output [B*N, 64]
__device__ float g_p1[128 * 64];        // mlp1 item partials [128][sum32|sq32]
__device__ float g_p2[256 * 128];       // mlp3 block partials [256][sum64|sq64]
__device__ int   g_fps[16384];          // [B, 2048]
__device__ float g_pooled[16384 * 68];  // [B*S][feat64 | xyz3 | pad]
__device__ float g_y3[16384 * 64];      // conv3 output [B*S, 64]

// ---------------- control state (re-zeroed each launch by init kernel) ----
__device__ int g_q;            // work-queue head
__device__ int g_done1;        // mlp1 items finished (target 128)
__device__ int g_done2;        // mlp2 items finished (target 256)
__device__ int g_smid_ready;   // how many FPS CTAs published their smid (target 8)
__device__ int g_prog[8];      // FPS progress per batch (# indices written)
__device__ int g_fps_sm[8];    // smid of each FPS CTA

__global__ void init_kernel() {
    int t = threadIdx.x;
    if (t == 0) { g_q = 0; g_done1 = 0; g_done2 = 0; g_smid_ready = 0; }
    if (t < 8) g_prog[t] = 0;
}

// ---------------- packed f32x2 helpers (per-lane .rn == scalar .rn) ----------------
__device__ __forceinline__ unsigned long long f2_add(unsigned long long a, unsigned long long b) {
    unsigned long long r;
    asm("add.rn.f32x2 %0, %1, %2;" : "=l"(r) : "l"(a), "l"(b));
    return r;
}
__device__ __forceinline__ unsigned long long f2_mul(unsigned long long a, unsigned long long b) {
    unsigned long long r;
    asm("mul.rn.f32x2 %0, %1, %2;" : "=l"(r) : "l"(a), "l"(b));
    return r;
}
__device__ __forceinline__ unsigned long long f2_pack(float lo, float hi) {
    unsigned long long r;
    asm("mov.b64 %0, {%1, %2};" : "=l"(r) : "f"(lo), "f"(hi));
    return r;
}
__device__ __forceinline__ float2 f2_unpack(unsigned long long v) {
    float2 f;
    asm("mov.b64 {%0, %1}, %2;" : "=f"(f.x), "=f"(f.y) : "l"(v));
    return f;
}

// =================================================================
// MEGA KERNEL: FPS (CTAs 0-7, one batch each) + work-queue workers
// queue: [0,128) mlp1 (256 pts) -> [128,384) mlp2 (128 pts)
//        -> [384,640) knn (64 queries)
// NOTE: no min-blocks in launch_bounds — FPS needs the full register
// budget (launch_bounds(256,2) capped at 128 regs and spilled the
// 2048-iteration FPS loop).
// =================================================================
__global__ void __launch_bounds__(256)
mega_kernel(const float* __restrict__ x,
            const float* __restrict__ W1, const float* __restrict__ b1,
            const float* __restrict__ W2, const float* __restrict__ b2,
            const float* __restrict__ g1, const float* __restrict__ be1) {
    extern __shared__ char smraw[];
    int tid = threadIdx.x;

    if (blockIdx.x < 8) {
        // ======================= FPS: one CTA per batch =======================
        float* px = (float*)smraw;           // [4096]
        float* py = px + 4096;
        float* pz = py + 4096;
        __shared__ unsigned rv[2][8], ri[2][8];
        int b = blockIdx.x;
        int lane = tid & 31, warp = tid >> 5;
        const float* xb = x + b * 12288;

        if (tid == 0) {
            unsigned sm_;
            asm("mov.u32 %0, %%smid;" : "=r"(sm_));
            g_fps_sm[b] = (int)sm_;
            __threadfence();
            atomicAdd(&g_smid_ready, 1);
        }

        // negated points in registers: dx = c + (-p); (-t)^2 == t^2 exactly
        unsigned long long NX[8], NY[8], NZ[8];
        float dd[16];
        #pragma unroll
        for (int k = 0; k < 8; k++) {
            int i = 2 * tid + 512 * k;
            float x0 = xb[3 * i],     y0 = xb[3 * i + 1], z0 = xb[3 * i + 2];
            float x1 = xb[3 * i + 3], y1 = xb[3 * i + 4], z1 = xb[3 * i + 5];
            px[i] = x0; py[i] = y0; pz[i] = z0;
            px[i + 1] = x1; py[i + 1] = y1; pz[i + 1] = z1;
            NX[k] = f2_pack(-x0, -x1); NY[k] = f2_pack(-y0, -y1); NZ[k] = f2_pack(-z0, -z1);
            dd[2 * k] = FLTMAX; dd[2 * k + 1] = FLTMAX;
        }
        __syncthreads();

        int far = 0;
        int* outp = g_fps + b * 2048;

        for (int s = 0; s < 2048; s++) {
            if (tid == 0) outp[s] = far;
            float cxs = px[far], cys = py[far], czs = pz[far];
            unsigned long long cx = f2_pack(cxs, cxs);
            unsigned long long cy = f2_pack(cys, cys);
            unsigned long long cz = f2_pack(czs, czs);
            #pragma unroll
            for (int k = 0; k < 8; k++) {
                unsigned long long dx = f2_add(NX[k], cx);
                unsigned long long dy = f2_add(NY[k], cy);
                unsigned long long dz = f2_add(NZ[k], cz);
                unsigned long long d = f2_add(f2_add(f2_mul(dx, dx), f2_mul(dy, dy)),
                                              f2_mul(dz, dz));
                float2 f = f2_unpack(d);
                dd[2 * k]     = fminf(dd[2 * k], f.x);
                dd[2 * k + 1] = fminf(dd[2 * k + 1], f.y);
            }
            // tree argmax over 16 slots (slot order == ascending global index;
            // strict > keeps lowest index on ties)
            float tv[16]; int ts[16];
            #pragma unroll
            for (int i = 0; i < 16; i++) { tv[i] = dd[i]; ts[i] = i; }
            #pragma unroll
            for (int off = 8; off; off >>= 1)
                #pragma unroll
                for (int i = 0; i < off; i++)
                    if (tv[i + off] > tv[i]) { tv[i] = tv[i + off]; ts[i] = ts[i + off]; }
            int slot = ts[0];
            int bi = 2 * tid + 512 * (slot >> 1) + (slot & 1);
            unsigned vb = __float_as_uint(tv[0]);

            unsigned wm = __reduce_max_sync(0xffffffffu, vb);
            unsigned cand = (vb == wm) ? (unsigned)bi : 0xffffffffu;
            unsigned wi = __reduce_min_sync(0xffffffffu, cand);
            int p = s & 1;
            if (lane == 0) { rv[p][warp] = wm; ri[p][warp] = wi; }
            __syncthreads();
            unsigned v  = rv[p][lane & 7];
            unsigned i2 = ri[p][lane & 7];
            unsigned m2 = __reduce_max_sync(0xffffffffu, v);
            unsigned c2 = (v == m2) ? i2 : 0xffffffffu;
            far = (int)__reduce_min_sync(0xffffffffu, c2);

            if (tid == 0 && (s & 31) == 31) {
                __threadfence();
                *(volatile int*)&g_prog[b] = s + 1;
            }
        }
        return;
    }

    // ======================= WORKERS =======================
    {
        unsigned mysm;
        asm("mov.u32 %0, %%smid;" : "=r"(mysm));
        while (*(volatile int*)&g_smid_ready < 8) __nanosleep(64);
        bool onfps = false;
        #pragma unroll
        for (int i = 0; i < 8; i++) onfps |= (g_fps_sm[i] == (int)mysm);
        if (onfps) return;   // keep FPS SMs uncontended
    }

    __shared__ int s_item;
    for (;;) {
        if (tid == 0) s_item = atomicAdd(&g_q, 1);
        __syncthreads();
        int it = s_item;
        __syncthreads();
        if (it >= 640) return;

        if (it < 128) {
            // ---------- mlp1 item: conv1(3->32)+BN1 partials, 256 pts ----------
            __shared__ float sW1[96], sb1[32], ssum[32], ssq[32];
            if (tid < 96) sW1[tid] = W1[tid];
            if (tid < 32) { sb1[tid] = b1[tid]; ssum[tid] = 0.0f; ssq[tid] = 0.0f; }
            __syncthreads();
            int p = it * 256 + tid;
            float X = x[3 * p], Y = x[3 * p + 1], Z = x[3 * p + 2];
            int lane = tid & 31;
            for (int c = 0; c < 32; c++) {
                float v = fmaf(sW1[3 * c + 2], Z,
                          fmaf(sW1[3 * c + 1], Y, fmaf(sW1[3 * c], X, sb1[c])));
                g_y1[p * 32 + c] = v;
                float sv = v, sq = v * v;
                #pragma unroll
                for (int off = 16; off; off >>= 1) {
                    sv += __shfl_down_sync(0xffffffffu, sv, off);
                    sq += __shfl_down_sync(0xffffffffu, sq, off);
                }
                if (lane == 0) { atomicAdd(&ssum[c], sv); atomicAdd(&ssq[c], sq); }
            }
            __syncthreads();
            if (tid < 32) {
                g_p1[it * 64 + tid] = ssum[tid];
                g_p1[it * 64 + 32 + tid] = ssq[tid];
            }
            __threadfence();
            __syncthreads();
            if (tid == 0) atomicAdd(&g_done1, 1);
        } else if (it < 384) {
            // ---------- mlp2 item: BN1+ReLU+conv2(32->64), 128 pts, transposed ----------
            int j = it - 128;                        // 0..255 -> covers all 32768 pts
            float* y1t = (float*)smraw;              // [128*32]
            float* W2s = (float*)smraw + 4096;       // [64*36] padded
            __shared__ float sc1[32], sh1[32], sb2[64];
            if (tid == 0) { while (*(volatile int*)&g_done1 < 128) __nanosleep(64); }
            __syncthreads();
            __threadfence();
            if (tid < 32) {
                float sum = 0.0f, sq = 0.0f;
                for (int k = 0; k < 128; k++) {
                    sum += g_p1[k * 64 + tid];
                    sq  += g_p1[k * 64 + 32 + tid];
                }
                float mean = sum / 32768.0f;
                float var  = sq / 32768.0f - mean * mean;
                float scl  = g1[tid] * rsqrtf(var + 1e-5f);
                sc1[tid] = scl;
                sh1[tid] = be1[tid] - mean * scl;
            }
            if (tid < 64) sb2[tid] = b2[tid];
            for (int i = tid; i < 2048; i += 256) {
                int o = i >> 5, c = i & 31;
                W2s[o * 36 + c] = W2[i];
            }
            __syncthreads();
            int p0 = j * 128;
            for (int i = tid; i < 4096; i += 256) {
                int c = i & 31;
                y1t[i] = fmaxf(fmaf(g_y1[p0 * 32 + i], sc1[c], sh1[c]), 0.0f);
            }
            __syncthreads();
            int o = tid & 63, q = tid >> 6;
            float acc[32];
            #pragma unroll
            for (int p = 0; p < 32; p++) acc[p] = sb2[o];
            const float4* wr = (const float4*)(W2s + o * 36);
            #pragma unroll
            for (int c4 = 0; c4 < 8; c4++) {
                float4 w = wr[c4];
                #pragma unroll
                for (int p = 0; p < 32; p++) {
                    float4 v = *(const float4*)(y1t + (q * 32 + p) * 32 + c4 * 4);
                    acc[p] = fmaf(w.x, v.x, fmaf(w.y, v.y,
                             fmaf(w.z, v.z, fmaf(w.w, v.w, acc[p]))));
                }
            }
            #pragma unroll
            for (int p = 0; p < 32; p++)
                g_feats[(p0 + q * 32 + p) * 64 + o] = acc[p];
            __threadfence();
            __syncthreads();
            if (tid == 0) atomicAdd(&g_done2, 1);
        } else {
            // ---------- knn item: 64 queries, 4 threads/query ----------
            int k = it - 384;
            int b = k & 7, grp = k >> 3;
            int s0 = grp * 64;
            float* sx = (float*)smraw;           // [1056]
            float* sy = sx + 1056;
            float* sz = sy + 1056;
            float* snn = sz + 1056;
            float2* mg = (float2*)(smraw + 16896);   // [64*64]
            int* klist = (int*)(smraw + 49664);      // [64*16]

            if (tid == 0) { while (*(volatile int*)&g_prog[b] < s0 + 64) __nanosleep(128); }
            __syncthreads();
            __threadfence();

            int r = tid & 3, ql = tid >> 2;
            int s = s0 + ql;
            const float* xb = x + b * 12288;
            int qi = g_fps[b * 2048 + s];
            float qx = xb[3 * qi], qy = xb[3 * qi + 1], qz = xb[3 * qi + 2];
            float qn = __fadd_rn(__fadd_rn(__fmul_rn(qx, qx), __fmul_rn(qy, qy)),
                                 __fmul_rn(qz, qz));
            unsigned long long qx2 = f2_pack(qx, qx), qy2 = f2_pack(qy, qy);
            unsigned long long qz2 = f2_pack(qz, qz);
            unsigned long long qn2 = f2_pack(qn, qn), n2 = f2_pack(-2.0f, -2.0f);

            float bd[16];
            int   bi[16];
            #pragma unroll
            for (int m = 0; m < 16; m++) { bd[m] = FLTMAX; bi[m] = 0x7fffffff; }
            float w = FLTMAX;
            int ws = 0;

            for (int t = 0; t < 4; t++) {
                __syncthreads();
                for (int jj = tid; jj < 1024; jj += 256) {
                    int i = t * 1024 + jj;
                    int slotp = (jj >> 8) * 264 + (jj & 255);
                    float X = xb[3 * i], Y = xb[3 * i + 1], Z = xb[3 * i + 2];
                    sx[slotp] = X; sy[slotp] = Y; sz[slotp] = Z;
                    snn[slotp] = __fadd_rn(__fadd_rn(__fmul_rn(X, X), __fmul_rn(Y, Y)),
                                           __fmul_rn(Z, Z));
                }
                __syncthreads();
                int qbase = r * 264;
                const float2* px2 = (const float2*)(sx + qbase);
                const float2* py2 = (const float2*)(sy + qbase);
                const float2* pz2 = (const float2*)(sz + qbase);
                const float2* pn2 = (const float2*)(snn + qbase);
                int base = t * 1024 + r * 256;
                for (int j2 = 0; j2 < 128; j2++) {
                    float2 vx = px2[j2], vy = py2[j2], vz = pz2[j2], vn = pn2[j2];
                    unsigned long long dot = f2_add(f2_add(f2_mul(qx2, f2_pack(vx.x, vx.y)),
                                                           f2_mul(qy2, f2_pack(vy.x, vy.y))),
                                                    f2_mul(qz2, f2_pack(vz.x, vz.y)));
                    unsigned long long d2 = f2_add(f2_add(qn2, f2_pack(vn.x, vn.y)),
                                                   f2_mul(dot, n2));
                    float2 d = f2_unpack(d2);
                    if (fminf(d.x, d.y) < w) {
                        #pragma unroll
                        for (int h = 0; h < 2; h++) {
                            float dv = h ? d.y : d.x;
                            if (dv < w) {
                                int i = base + 2 * j2 + h;
                                #pragma unroll
                                for (int m = 0; m < 16; m++)
                                    if (m == ws) { bd[m] = dv; bi[m] = i; }
                                float nw = -FLTMAX; int nwi = -1; int nws = 0;
                                #pragma unroll
                                for (int m = 0; m < 16; m++) {
                                    bool better = (bd[m] > nw) || (bd[m] == nw && bi[m] > nwi);
                                    if (better) { nw = bd[m]; nwi = bi[m]; nws = m; }
                                }
                                w = nw; ws = nws;
                            }
                        }
                    }
                }
            }

            // 4-way rank merge over disjoint-index union of 64 candidates
            __syncthreads();
            #pragma unroll
            for (int m = 0; m < 16; m++)
                mg[ql * 64 + r * 16 + m] = make_float2(bd[m], __int_as_float(bi[m]));
            __syncwarp();
            int rank[16];
            #pragma unroll
            for (int m = 0; m < 16; m++) rank[m] = 0;
            const float2* u = &mg[ql * 64];
            for (int e = 0; e < 64; e++) {
                float2 pe = u[e];
                int pi = __float_as_int(pe.y);
                #pragma unroll
                for (int m = 0; m < 16; m++)
                    rank[m] += (pe.x < bd[m]) || (pe.x == bd[m] && pi < bi[m]);
            }
            int* kl = &klist[ql * 16];
            #pragma unroll
            for (int m = 0; m < 16; m++)
                if (rank[m] < 16) kl[rank[m]] = bi[m];
            __syncwarp();

            int idx16[16];
            #pragma unroll
            for (int kk = 0; kk < 16; kk++) idx16[kk] = kl[kk];

            // wait for all feats before gather
            __syncthreads();
            if (tid == 0) { while (*(volatile int*)&g_done2 < 256) __nanosleep(128); }
            __syncthreads();
            __threadfence();

            float* op = g_pooled + (b * 2048 + s) * 68;
            if (r == 0) {
                float mx = -FLTMAX, my = -FLTMAX, mz = -FLTMAX;
                #pragma unroll
                for (int kk = 0; kk < 16; kk++) {
                    int i = idx16[kk];
                    mx = fmaxf(mx, __fsub_rn(xb[3 * i], qx));
                    my = fmaxf(my, __fsub_rn(xb[3 * i + 1], qy));
                    mz = fmaxf(mz, __fsub_rn(xb[3 * i + 2], qz));
                }
                op[64] = mx; op[65] = my; op[66] = mz; op[67] = 0.0f;
            }
            const float* fb = g_feats + b * 4096 * 64 + r * 16;
            float4 acc[4];
            #pragma unroll
            for (int q = 0; q < 4; q++)
                acc[q] = make_float4(-FLTMAX, -FLTMAX, -FLTMAX, -FLTMAX);
            #pragma unroll
            for (int kk = 0; kk < 16; kk++) {
                const float4* fr = (const float4*)(fb + idx16[kk] * 64);
                #pragma unroll
                for (int q = 0; q < 4; q++) {
                    float4 f = fr[q];
                    acc[q].x = fmaxf(acc[q].x, f.x);
                    acc[q].y = fmaxf(acc[q].y, f.y);
                    acc[q].z = fmaxf(acc[q].z, f.z);
                    acc[q].w = fmaxf(acc[q].w, f.w);
                }
            }
            float4* of = (float4*)(op + r * 16);
            #pragma unroll
            for (int q = 0; q < 4; q++) of[q] = acc[q];
            __syncthreads();
        }
    }
}

// ---------------- mlp3: conv3(67->64) transposed + BN2 partials ----------------
__global__ void __launch_bounds__(128) mlp3_kernel(const float* __restrict__ W3,
                                                   const float* __restrict__ b3) {
    __shared__ float P[64 * 68];
    __shared__ float W[64 * 68];
    __shared__ float sb[64];
    __shared__ float red[128];
    int tid = threadIdx.x;
    for (int i = tid; i < 64 * 68; i += 128) {
        int o = i / 68, c = i - o * 68;
        W[i] = (c < 64) ? W3[o * 67 + 3 + c] : ((c < 67) ? W3[o * 67 + (c - 64)] : 0.0f);
    }
    if (tid < 64) sb[tid] = b3[tid];
    int p0 = blockIdx.x * 64;
    for (int i = tid; i < 64 * 68; i += 128) P[i] = g_pooled[p0 * 68 + i];
    __syncthreads();
    int o = tid & 63, h = tid >> 6;
    float acc[32];
    #pragma unroll
    for (int p = 0; p < 32; p++) acc[p] = sb[o];
    const float4* wr = (const float4*)(W + o * 68);
    #pragma unroll
    for (int c4 = 0; c4 < 17; c4++) {
        float4 w = wr[c4];
        #pragma unroll
        for (int p = 0; p < 32; p++) {
            float4 v = *(const float4*)(P + (h * 32 + p) * 68 + c4 * 4);
            acc[p] = fmaf(w.x, v.x, fmaf(w.y, v.y, fmaf(w.z, v.z, fmaf(w.w, v.w, acc[p]))));
        }
    }
    float ssum = 0.0f, ssq = 0.0f;
    #pragma unroll
    for (int p = 0; p < 32; p++) {
        g_y3[(p0 + h * 32 + p) * 64 + o] = acc[p];
        ssum += acc[p]; ssq += acc[p] * acc[p];
    }
    red[tid] = ssum;
    __syncthreads();
    if (tid < 64) g_p2[blockIdx.x * 128 + tid] = red[tid] + red[tid + 64];
    __syncthreads();
    red[tid] = ssq;
    __syncthreads();
    if (tid < 64) g_p2[blockIdx.x * 128 + 64 + tid] = red[tid] + red[tid + 64];
}

// ---------------- mlp4: BN2 finalize (in-block) + ReLU + conv4 -> out ----------------
__global__ void __launch_bounds__(128) mlp4_kernel(const float* __restrict__ W4,
                                                   const float* __restrict__ b4,
                                                   const float* __restrict__ g2,
                                                   const float* __restrict__ be2,
                                                   float* __restrict__ out) {
    __shared__ float Y[64 * 64];
    __shared__ float W[64 * 68];
    __shared__ float sb[64], sc[64], sh[64];
    int tid = threadIdx.x;
    if (tid < 64) {
        sb[tid] = b4[tid];
        float sum = 0.0f, sq = 0.0f;
        for (int k = 0; k < 256; k++) {
            sum += g_p2[k * 128 + tid];
            sq  += g_p2[k * 128 + 64 + tid];
        }
        float mean = sum / 16384.0f;
        float var  = sq / 16384.0f - mean * mean;
        float scl  = g2[tid] * rsqrtf(var + 1e-5f);
        sc[tid] = scl;
        sh[tid] = be2[tid] - mean * scl;
    }
    for (int i = tid; i < 64 * 68; i += 128) {
        int o = i / 68, c = i - o * 68;
        W[i] = (c < 64) ? W4[o * 64 + c] : 0.0f;
    }
    __syncthreads();
    int p0 = blockIdx.x * 64;
    for (int i = tid; i < 4096; i += 128) {
        int c = i & 63;
        Y[i] = fmaxf(fmaf(g_y3[p0 * 64 + i], sc[c], sh[c]), 0.0f);
    }
    __syncthreads();
    int o = tid & 63, h = tid >> 6;
    float acc[32];
    #pragma unroll
    for (int p = 0; p < 32; p++) acc[p] = sb[o];
    const float4* wr = (const float4*)(W + o * 68);
    #pragma unroll
    for (int c4 = 0; c4 < 16; c4++) {
        float4 w = wr[c4];
        #pragma unroll
        for (int p = 0; p < 32; p++) {
            float4 v = *(const float4*)(Y + (h * 32 + p) * 64 + c4 * 4);
            acc[p] = fmaf(w.x, v.x, fmaf(w.y, v.y, fmaf(w.z, v.z, fmaf(w.w, v.w, acc[p]))));
        }
    }
    #pragma unroll
    for (int p = 0; p < 32; p++)
        out[(p0 + h * 32 + p) * 64 + o] = acc[p];
}

// ---------------- launch ----------------
extern "C" void kernel_launch(void* const* d_in, const int* in_sizes, int n_in,
                              void* d_out, int out_size) {
    const float* x   = (const float*)d_in[0];
    const float* W1  = (const float*)d_in[1];
    const float* b1  = (const float*)d_in[2];
    const float* g1  = (const float*)d_in[3];
    const float* be1 = (const float*)d_in[4];
    const float* W2  = (const float*)d_in[5];
    const float* b2  = (const float*)d_in[6];
    const float* W3  = (const float*)d_in[7];
    const float* b3  = (const float*)d_in[8];
    const float* g2  = (const float*)d_in[9];
    const float* be2 = (const float*)d_in[10];
    const float* W4  = (const float*)d_in[11];
    const float* b4  = (const float*)d_in[12];
    float* out = (float*)d_out;

    cudaFuncSetAttribute(mega_kernel, cudaFuncAttributeMaxDynamicSharedMemorySize, 53760);

    init_kernel<<<1, 32>>>();
    mega_kernel<<<296, 256, 53760>>>(x, W1, b1, W2, b2, g1, be1);
    mlp3_kernel<<<256, 128>>>(W3, b3);
    mlp4_kernel<<<256, 128>>>(W4, b4, g2, be2, out);
}

// round 10
// speedup vs baseline: 1.4704x; 1.0006x over previous
#include <cuda_runtime.h>

#define FLTMAX 3.402823466e+38f

// ---------------- device scratch ----------------
__device__ float g_y1[32768 * 32];      // conv1 output [B*N, 32]
__device__ float g_feats[32768 * 64];   // conv2 output [B*N, 64]
__device__ float g_p1[64 * 64];         // mlp1 block partials [64][sum32|sq32]
__device__ float g_p2[256 * 128];       // mlp3 block partials [256][sum64|sq64]
__device__ int   g_fps[16384];          // [B, 2048]
__device__ float g_pooled[16384 * 68];  // [B*S][feat64 | xyz3 | pad]
__device__ float g_y3[16384 * 64];      // conv3 output [B*S, 64]

// ---------------- packed f32x2 helpers (per-lane .rn == scalar .rn) ----------------
__device__ __forceinline__ unsigned long long f2_add(unsigned long long a, unsigned long long b) {
    unsigned long long r;
    asm("add.rn.f32x2 %0, %1, %2;" : "=l"(r) : "l"(a), "l"(b));
    return r;
}
__device__ __forceinline__ unsigned long long f2_mul(unsigned long long a, unsigned long long b) {
    unsigned long long r;
    asm("mul.rn.f32x2 %0, %1, %2;" : "=l"(r) : "l"(a), "l"(b));
    return r;
}
__device__ __forceinline__ unsigned long long f2_pack(float lo, float hi) {
    unsigned long long r;
    asm("mov.b64 %0, {%1, %2};" : "=l"(r) : "f"(lo), "f"(hi));
    return r;
}
__device__ __forceinline__ float2 f2_unpack(unsigned long long v) {
    float2 f;
    asm("mov.b64 {%0, %1}, %2;" : "=f"(f.x), "=f"(f.y) : "l"(v));
    return f;
}

// =================================================================
// fused FPS (blocks 0-7, 512 thr) + mlp1 (blocks 8-71, 512 pts each)
// FPS: thread t owns contiguous points [8t, 8t+8) ->
//   - local argmax if-chain keeps lowest slot (== lowest index)
//   - warp argmax: redux_max + ballot + ffs (lowest lane == lowest index)
//   - 16 warp partials: warp w owns [256w,256w+256) so min-index redux is exact
// =================================================================
__global__ void __launch_bounds__(512)
fps_mlp1_kernel(const float* __restrict__ x, const float* __restrict__ W1,
                const float* __restrict__ b1) {
    extern __shared__ char smraw[];
    int tid = threadIdx.x;

    if (blockIdx.x < 8) {
        float* px = (float*)smraw;           // [4096]
        float* py = px + 4096;
        float* pz = py + 4096;
        __shared__ unsigned rv[2][16], ri[2][16];
        int b = blockIdx.x;
        int lane = tid & 31, warp = tid >> 5;
        const float* xb = x + b * 12288;

        // negated points in registers: dx = c + (-p); (-t)^2 == t^2 exactly
        unsigned long long NX[4], NY[4], NZ[4];
        float dd[8];
        #pragma unroll
        for (int k = 0; k < 4; k++) {
            int i = 8 * tid + 2 * k;
            float x0 = xb[3 * i],     y0 = xb[3 * i + 1], z0 = xb[3 * i + 2];
            float x1 = xb[3 * i + 3], y1 = xb[3 * i + 4], z1 = xb[3 * i + 5];
            px[i] = x0; py[i] = y0; pz[i] = z0;
            px[i + 1] = x1; py[i + 1] = y1; pz[i + 1] = z1;
            NX[k] = f2_pack(-x0, -x1); NY[k] = f2_pack(-y0, -y1); NZ[k] = f2_pack(-z0, -z1);
            dd[2 * k] = FLTMAX; dd[2 * k + 1] = FLTMAX;
        }
        __syncthreads();

        int far = 0;
        int* outp = g_fps + b * 2048;

        for (int s = 0; s < 2048; s++) {
            if (tid == 0) outp[s] = far;
            float cxs = px[far], cys = py[far], czs = pz[far];
            unsigned long long cx = f2_pack(cxs, cxs);
            unsigned long long cy = f2_pack(cys, cys);
            unsigned long long cz = f2_pack(czs, czs);
            #pragma unroll
            for (int k = 0; k < 4; k++) {
                unsigned long long dx = f2_add(NX[k], cx);
                unsigned long long dy = f2_add(NY[k], cy);
                unsigned long long dz = f2_add(NZ[k], cz);
                unsigned long long d = f2_add(f2_add(f2_mul(dx, dx), f2_mul(dy, dy)),
                                              f2_mul(dz, dz));
                float2 f = f2_unpack(d);
                dd[2 * k]     = fminf(dd[2 * k], f.x);
                dd[2 * k + 1] = fminf(dd[2 * k + 1], f.y);
            }
            // local argmax over 8 contiguous slots (strict > keeps lowest index)
            float bv = dd[0]; int bs = 0;
            #pragma unroll
            for (int j = 1; j < 8; j++)
                if (dd[j] > bv) { bv = dd[j]; bs = j; }
            int bi = 8 * tid + bs;

            // warp argmax: redux + ballot (lowest lane == lowest global index)
            unsigned vb = __float_as_uint(bv);
            unsigned wm = __reduce_max_sync(0xffffffffu, vb);
            unsigned mask = __ballot_sync(0xffffffffu, vb == wm);
            int src = __ffs(mask) - 1;
            int wi = __shfl_sync(0xffffffffu, bi, src);

            int p = s & 1;
            if (lane == 0) { rv[p][warp] = wm; ri[p][warp] = (unsigned)wi; }
            __syncthreads();
            // final reduce over 16 warp partials (all warps redundantly);
            // warp index ranges ascend, so min candidate index is exact tie-break
            unsigned v  = rv[p][lane & 15];
            unsigned i2 = ri[p][lane & 15];
            unsigned m2 = __reduce_max_sync(0xffffffffu, v);
            unsigned c2 = (v == m2) ? i2 : 0xffffffffu;
            far = (int)__reduce_min_sync(0xffffffffu, c2);
        }
    } else {
        // ======== mlp1: conv1 (3->32) + BN1 partial stats, 1 point/thread ========
        __shared__ float sW1[96], sb1[32], ssum[32], ssq[32];
        int blk = blockIdx.x - 8;
        if (tid < 96) sW1[tid] = W1[tid];
        if (tid < 32) { sb1[tid] = b1[tid]; ssum[tid] = 0.0f; ssq[tid] = 0.0f; }
        __syncthreads();
        int p = blk * 512 + tid;
        float X = x[3 * p], Y = x[3 * p + 1], Z = x[3 * p + 2];
        int lane = tid & 31;
        for (int c = 0; c < 32; c++) {
            float v = fmaf(sW1[3 * c + 2], Z,
                      fmaf(sW1[3 * c + 1], Y, fmaf(sW1[3 * c], X, sb1[c])));
            g_y1[p * 32 + c] = v;
            float sv = v, sq = v * v;
            #pragma unroll
            for (int off = 16; off; off >>= 1) {
                sv += __shfl_down_sync(0xffffffffu, sv, off);
                sq += __shfl_down_sync(0xffffffffu, sq, off);
            }
            if (lane == 0) { atomicAdd(&ssum[c], sv); atomicAdd(&ssq[c], sq); }
        }
        __syncthreads();
        if (tid < 32) {
            g_p1[blk * 64 + tid] = ssum[tid];
            g_p1[blk * 64 + 32 + tid] = ssq[tid];
        }
    }
}

// ---------------- mlp2: BN1 finalize + ReLU + conv2 (32->64), transposed ----------------
__global__ void __launch_bounds__(256) mlp2_kernel(const float* __restrict__ W2,
                                                   const float* __restrict__ b2,
                                                   const float* __restrict__ g1,
                                                   const float* __restrict__ be1) {
    __shared__ float y1t[128 * 32];
    __shared__ float W2s[64 * 36];
    __shared__ float sc1[32], sh1[32], sb2[64];
    int tid = threadIdx.x;
    if (tid < 32) {
        float sum = 0.0f, sq = 0.0f;
        for (int k = 0; k < 64; k++) {
            sum += g_p1[k * 64 + tid];
            sq  += g_p1[k * 64 + 32 + tid];
        }
        float mean = sum / 32768.0f;
        float var  = sq / 32768.0f - mean * mean;
        float scl  = g1[tid] * rsqrtf(var + 1e-5f);
        sc1[tid] = scl;
        sh1[tid] = be1[tid] - mean * scl;
    }
    if (tid < 64) sb2[tid] = b2[tid];
    for (int i = tid; i < 2048; i += 256) {
        int o = i >> 5, c = i & 31;
        W2s[o * 36 + c] = W2[i];
    }
    __syncthreads();
    int p0 = blockIdx.x * 128;
    for (int i = tid; i < 4096; i += 256) {
        int c = i & 31;
        y1t[i] = fmaxf(fmaf(g_y1[p0 * 32 + i], sc1[c], sh1[c]), 0.0f);
    }
    __syncthreads();
    int o = tid & 63, q = tid >> 6;
    float acc[32];
    #pragma unroll
    for (int p = 0; p < 32; p++) acc[p] = sb2[o];
    const float4* wr = (const float4*)(W2s + o * 36);
    #pragma unroll
    for (int c4 = 0; c4 < 8; c4++) {
        float4 w = wr[c4];
        #pragma unroll
        for (int p = 0; p < 32; p++) {
            float4 v = *(const float4*)(y1t + (q * 32 + p) * 32 + c4 * 4);
            acc[p] = fmaf(w.x, v.x, fmaf(w.y, v.y, fmaf(w.z, v.z, fmaf(w.w, v.w, acc[p]))));
        }
    }
    #pragma unroll
    for (int p = 0; p < 32; p++)
        g_feats[(p0 + q * 32 + p) * 64 + o] = acc[p];
}

// ---------------- 16-NN + group + maxpool: 4 threads per query (R4 verbatim) ----------------
__global__ void __launch_bounds__(128) knn_pool_kernel(const float* __restrict__ x) {
    __shared__ float sx[1056], sy[1056], sz[1056], sn[1056];
    __shared__ float2 mg[32 * 64];
    __shared__ int klist[32 * 16];
    int b = blockIdx.y;
    int tid = threadIdx.x;
    int r = tid & 3;
    int ql = tid >> 2;
    int s = blockIdx.x * 32 + ql;
    const float* xb = x + b * 12288;
    int qi = g_fps[b * 2048 + s];
    float qx = xb[3 * qi], qy = xb[3 * qi + 1], qz = xb[3 * qi + 2];
    float qn = __fadd_rn(__fadd_rn(__fmul_rn(qx, qx), __fmul_rn(qy, qy)), __fmul_rn(qz, qz));
    unsigned long long qx2 = f2_pack(qx, qx), qy2 = f2_pack(qy, qy), qz2 = f2_pack(qz, qz);
    unsigned long long qn2 = f2_pack(qn, qn), n2 = f2_pack(-2.0f, -2.0f);

    float bd[16];
    int   bi[16];
    #pragma unroll
    for (int m = 0; m < 16; m++) { bd[m] = FLTMAX; bi[m] = 0x7fffffff; }
    float w = FLTMAX;
    int ws = 0;

    for (int t = 0; t < 4; t++) {
        __syncthreads();
        for (int j = tid; j < 1024; j += 128) {
            int i = t * 1024 + j;
            int slot = (j >> 8) * 264 + (j & 255);
            float X = xb[3 * i], Y = xb[3 * i + 1], Z = xb[3 * i + 2];
            sx[slot] = X; sy[slot] = Y; sz[slot] = Z;
            sn[slot] = __fadd_rn(__fadd_rn(__fmul_rn(X, X), __fmul_rn(Y, Y)), __fmul_rn(Z, Z));
        }
        __syncthreads();
        int qbase = r * 264;
        const float2* px2 = (const float2*)(sx + qbase);
        const float2* py2 = (const float2*)(sy + qbase);
        const float2* pz2 = (const float2*)(sz + qbase);
        const float2* pn2 = (const float2*)(sn + qbase);
        int base = t * 1024 + r * 256;
        for (int j2 = 0; j2 < 128; j2++) {
            float2 vx = px2[j2], vy = py2[j2], vz = pz2[j2], vn = pn2[j2];
            unsigned long long dot = f2_add(f2_add(f2_mul(qx2, f2_pack(vx.x, vx.y)),
                                                   f2_mul(qy2, f2_pack(vy.x, vy.y))),
                                            f2_mul(qz2, f2_pack(vz.x, vz.y)));
            unsigned long long d2 = f2_add(f2_add(qn2, f2_pack(vn.x, vn.y)), f2_mul(dot, n2));
            float2 d = f2_unpack(d2);
            if (fminf(d.x, d.y) < w) {
                #pragma unroll
                for (int h = 0; h < 2; h++) {
                    float dv = h ? d.y : d.x;
                    if (dv < w) {
                        int i = base + 2 * j2 + h;
                        #pragma unroll
                        for (int m = 0; m < 16; m++)
                            if (m == ws) { bd[m] = dv; bi[m] = i; }
                        float nw = -FLTMAX; int nwi = -1; int nws = 0;
                        #pragma unroll
                        for (int m = 0; m < 16; m++) {
                            bool better = (bd[m] > nw) || (bd[m] == nw && bi[m] > nwi);
                            if (better) { nw = bd[m]; nwi = bi[m]; nws = m; }
                        }
                        w = nw; ws = nws;
                    }
                }
            }
        }
    }

    __syncthreads();
    #pragma unroll
    for (int m = 0; m < 16; m++)
        mg[ql * 64 + r * 16 + m] = make_float2(bd[m], __int_as_float(bi[m]));
    __syncwarp();
    int rank[16];
    #pragma unroll
    for (int m = 0; m < 16; m++) rank[m] = 0;
    const float2* u = &mg[ql * 64];
    for (int e = 0; e < 64; e++) {
        float2 pe = u[e];
        int pi = __float_as_int(pe.y);
        #pragma unroll
        for (int m = 0; m < 16; m++)
            rank[m] += (pe.x < bd[m]) || (pe.x == bd[m] && pi < bi[m]);
    }
    int* kl = &klist[ql * 16];
    #pragma unroll
    for (int m = 0; m < 16; m++)
        if (rank[m] < 16) kl[rank[m]] = bi[m];
    __syncwarp();

    int idx16[16];
    #pragma unroll
    for (int k = 0; k < 16; k++) idx16[k] = kl[k];

    float* op = g_pooled + (b * 2048 + s) * 68;

    if (r == 0) {
        float mx = -FLTMAX, my = -FLTMAX, mz = -FLTMAX;
        #pragma unroll
        for (int k = 0; k < 16; k++) {
            int i = idx16[k];
            mx = fmaxf(mx, __fsub_rn(xb[3 * i], qx));
            my = fmaxf(my, __fsub_rn(xb[3 * i + 1], qy));
            mz = fmaxf(mz, __fsub_rn(xb[3 * i + 2], qz));
        }
        op[64] = mx; op[65] = my; op[66] = mz; op[67] = 0.0f;
    }

    const float* fb = g_feats + b * 4096 * 64 + r * 16;
    float4 acc[4];
    #pragma unroll
    for (int q = 0; q < 4; q++) acc[q] = make_float4(-FLTMAX, -FLTMAX, -FLTMAX, -FLTMAX);
    #pragma unroll
    for (int k = 0; k < 16; k++) {
        const float4* fr = (const float4*)(fb + idx16[k] * 64);
        #pragma unroll
        for (int q = 0; q < 4; q++) {
            float4 f = fr[q];
            acc[q].x = fmaxf(acc[q].x, f.x);
            acc[q].y = fmaxf(acc[q].y, f.y);
            acc[q].z = fmaxf(acc[q].z, f.z);
            acc[q].w = fmaxf(acc[q].w, f.w);
        }
    }
    float4* of = (float4*)(op + r * 16);
    #pragma unroll
    for (int q = 0; q < 4; q++) of[q] = acc[q];
}

// ---------------- mlp3: conv3(67->64) transposed + BN2 partials ----------------
__global__ void __launch_bounds__(128) mlp3_kernel(const float* __restrict__ W3,
                                                   const float* __restrict__ b3) {
    __shared__ float P[64 * 68];
    __shared__ float W[64 * 68];
    __shared__ float sb[64];
    __shared__ float red[128];
    int tid = threadIdx.x;
    for (int i = tid; i < 64 * 68; i += 128) {
        int o = i / 68, c = i - o * 68;
        W[i] = (c < 64) ? W3[o * 67 + 3 + c] : ((c < 67) ? W3[o * 67 + (c - 64)] : 0.0f);
    }
    if (tid < 64) sb[tid] = b3[tid];
    int p0 = blockIdx.x * 64;
    for (int i = tid; i < 64 * 68; i += 128) P[i] = g_pooled[p0 * 68 + i];
    __syncthreads();
    int o = tid & 63, h = tid >> 6;
    float acc[32];
    #pragma unroll
    for (int p = 0; p < 32; p++) acc[p] = sb[o];
    const float4* wr = (const float4*)(W + o * 68);
    #pragma unroll
    for (int c4 = 0; c4 < 17; c4++) {
        float4 w = wr[c4];
        #pragma unroll
        for (int p = 0; p < 32; p++) {
            float4 v = *(const float4*)(P + (h * 32 + p) * 68 + c4 * 4);
            acc[p] = fmaf(w.x, v.x, fmaf(w.y, v.y, fmaf(w.z, v.z, fmaf(w.w, v.w, acc[p]))));
        }
    }
    float ssum = 0.0f, ssq = 0.0f;
    #pragma unroll
    for (int p = 0; p < 32; p++) {
        g_y3[(p0 + h * 32 + p) * 64 + o] = acc[p];
        ssum += acc[p]; ssq += acc[p] * acc[p];
    }
    red[tid] = ssum;
    __syncthreads();
    if (tid < 64) g_p2[blockIdx.x * 128 + tid] = red[tid] + red[tid + 64];
    __syncthreads();
    red[tid] = ssq;
    __syncthreads();
    if (tid < 64) g_p2[blockIdx.x * 128 + 64 + tid] = red[tid] + red[tid + 64];
}

// ---------------- mlp4: BN2 finalize (in-block) + ReLU + conv4 -> out ----------------
__global__ void __launch_bounds__(128) mlp4_kernel(const float* __restrict__ W4,
                                                   const float* __restrict__ b4,
                                                   const float* __restrict__ g2,
                                                   const float* __restrict__ be2,
                                                   float* __restrict__ out) {
    __shared__ float Y[64 * 64];
    __shared__ float W[64 * 68];
    __shared__ float sb[64], sc[64], sh[64];
    int tid = threadIdx.x;
    if (tid < 64) {
        sb[tid] = b4[tid];
        float sum = 0.0f, sq = 0.0f;
        for (int k = 0; k < 256; k++) {
            sum += g_p2[k * 128 + tid];
            sq  += g_p2[k * 128 + 64 + tid];
        }
        float mean = sum / 16384.0f;
        float var  = sq / 16384.0f - mean * mean;
        float scl  = g2[tid] * rsqrtf(var + 1e-5f);
        sc[tid] = scl;
        sh[tid] = be2[tid] - mean * scl;
    }
    for (int i = tid; i < 64 * 68; i += 128) {
        int o = i / 68, c = i - o * 68;
        W[i] = (c < 64) ? W4[o * 64 + c] : 0.0f;
    }
    __syncthreads();
    int p0 = blockIdx.x * 64;
    for (int i = tid; i < 4096; i += 128) {
        int c = i & 63;
        Y[i] = fmaxf(fmaf(g_y3[p0 * 64 + i], sc[c], sh[c]), 0.0f);
    }
    __syncthreads();
    int o = tid & 63, h = tid >> 6;
    float acc[32];
    #pragma unroll
    for (int p = 0; p < 32; p++) acc[p] = sb[o];
    const float4* wr = (const float4*)(W + o * 68);
    #pragma unroll
    for (int c4 = 0; c4 < 16; c4++) {
        float4 w = wr[c4];
        #pragma unroll
        for (int p = 0; p < 32; p++) {
            float4 v = *(const float4*)(Y + (h * 32 + p) * 64 + c4 * 4);
            acc[p] = fmaf(w.x, v.x, fmaf(w.y, v.y, fmaf(w.z, v.z, fmaf(w.w, v.w, acc[p]))));
        }
    }
    #pragma unroll
    for (int p = 0; p < 32; p++)
        out[(p0 + h * 32 + p) * 64 + o] = acc[p];
}

// ---------------- launch ----------------
extern "C" void kernel_launch(void* const* d_in, const int* in_sizes, int n_in,
                              void* d_out, int out_size) {
    const float* x   = (const float*)d_in[0];
    const float* W1  = (const float*)d_in[1];
    const float* b1  = (const float*)d_in[2];
    const float* g1  = (const float*)d_in[3];
    const float* be1 = (const float*)d_in[4];
    const float* W2  = (const float*)d_in[5];
    const float* b2  = (const float*)d_in[6];
    const float* W3  = (const float*)d_in[7];
    const float* b3  = (const float*)d_in[8];
    const float* g2  = (const float*)d_in[9];
    const float* be2 = (const float*)d_in[10];
    const float* W4  = (const float*)d_in[11];
    const float* b4  = (const float*)d_in[12];
    float* out = (float*)d_out;

    cudaFuncSetAttribute(fps_mlp1_kernel, cudaFuncAttributeMaxDynamicSharedMemorySize, 49152);

    fps_mlp1_kernel<<<72, 512, 49152>>>(x, W1, b1);   // FPS (8 CTAs) || mlp1 (64 CTAs)
    mlp2_kernel<<<256, 256>>>(W2, b2, g1, be1);
    knn_pool_kernel<<<dim3(64, 8), 128>>>(x);
    mlp3_kernel<<<256, 128>>>(W3, b3);
    mlp4_kernel<<<256, 128>>>(W4, b4, g2, be2, out);
}

// round 11
// speedup vs baseline: 1.5984x; 1.0871x over previous
#include <cuda_runtime.h>

#define FLTMAX 3.402823466e+38f

// ---------------- device scratch ----------------
__device__ float g_y1[32768 * 32];      // conv1 output [B*N, 32]
__device__ float g_feats[32768 * 64];   // conv2 output [B*N, 64]
__device__ float g_p1[128 * 64];        // mlp1 item partials [128][sum32|sq32]
__device__ float g_p2[256 * 128];       // mlp3 block partials [256][sum64|sq64]
__device__ int   g_fps[16384];          // [B, 2048]
__device__ float g_pooled[16384 * 68];  // [B*S][feat64 | xyz3 | pad]
__device__ float g_y3[16384 * 64];      // conv3 output [B*S, 64]

// ---------------- control state (re-zeroed each launch by init kernel) ----
__device__ int g_q;            // work-queue head
__device__ int g_done1;        // mlp1 items finished (target 128)
__device__ int g_done2;        // mlp2 items finished (target 256)
__device__ int g_smid_ready;   // how many FPS CTAs published their smid (target 8)
__device__ int g_prog[8];      // FPS progress per batch (# indices written)
__device__ int g_fps_sm[8];    // smid of each FPS CTA

__global__ void init_kernel() {
    int t = threadIdx.x;
    if (t == 0) { g_q = 0; g_done1 = 0; g_done2 = 0; g_smid_ready = 0; }
    if (t < 8) g_prog[t] = 0;
}

// ---------------- packed f32x2 helpers (per-lane .rn == scalar .rn) ----------------
__device__ __forceinline__ unsigned long long f2_add(unsigned long long a, unsigned long long b) {
    unsigned long long r;
    asm("add.rn.f32x2 %0, %1, %2;" : "=l"(r) : "l"(a), "l"(b));
    return r;
}
__device__ __forceinline__ unsigned long long f2_mul(unsigned long long a, unsigned long long b) {
    unsigned long long r;
    asm("mul.rn.f32x2 %0, %1, %2;" : "=l"(r) : "l"(a), "l"(b));
    return r;
}
__device__ __forceinline__ unsigned long long f2_pack(float lo, float hi) {
    unsigned long long r;
    asm("mov.b64 %0, {%1, %2};" : "=l"(r) : "f"(lo), "f"(hi));
    return r;
}
__device__ __forceinline__ float2 f2_unpack(unsigned long long v) {
    float2 f;
    asm("mov.b64 {%0, %1}, %2;" : "=f"(f.x), "=f"(f.y) : "l"(v));
    return f;
}

// =================================================================
// MEGA KERNEL: FPS (CTAs 0-7, one batch each) + work-queue workers
// queue: [0,128) mlp1 (256 pts) -> [128,384) mlp2 (128 pts)
//        -> [384,640) knn (64 queries)
// =================================================================
__global__ void __launch_bounds__(256, 2)
mega_kernel(const float* __restrict__ x,
            const float* __restrict__ W1, const float* __restrict__ b1,
            const float* __restrict__ W2, const float* __restrict__ b2,
            const float* __restrict__ g1, const float* __restrict__ be1) {
    extern __shared__ char smraw[];
    int tid = threadIdx.x;

    if (blockIdx.x < 8) {
        // ======================= FPS: one CTA per batch =======================
        float* px = (float*)smraw;           // [4096]
        float* py = px + 4096;
        float* pz = py + 4096;
        __shared__ unsigned rv[2][8], ri[2][8];
        int b = blockIdx.x;
        int lane = tid & 31, warp = tid >> 5;
        const float* xb = x + b * 12288;

        if (tid == 0) {
            unsigned sm_;
            asm("mov.u32 %0, %%smid;" : "=r"(sm_));
            g_fps_sm[b] = (int)sm_;
            __threadfence();
            atomicAdd(&g_smid_ready, 1);
        }

        // negated points in registers: dx = c + (-p); (-t)^2 == t^2 exactly
        unsigned long long NX[8], NY[8], NZ[8];
        float dd[16];
        #pragma unroll
        for (int k = 0; k < 8; k++) {
            int i = 2 * tid + 512 * k;
            float x0 = xb[3 * i],     y0 = xb[3 * i + 1], z0 = xb[3 * i + 2];
            float x1 = xb[3 * i + 3], y1 = xb[3 * i + 4], z1 = xb[3 * i + 5];
            px[i] = x0; py[i] = y0; pz[i] = z0;
            px[i + 1] = x1; py[i + 1] = y1; pz[i + 1] = z1;
            NX[k] = f2_pack(-x0, -x1); NY[k] = f2_pack(-y0, -y1); NZ[k] = f2_pack(-z0, -z1);
            dd[2 * k] = FLTMAX; dd[2 * k + 1] = FLTMAX;
        }
        __syncthreads();

        int far = 0;
        int* outp = g_fps + b * 2048;

        for (int s = 0; s < 2048; s++) {
            if (tid == 0) outp[s] = far;
            float cxs = px[far], cys = py[far], czs = pz[far];
            unsigned long long cx = f2_pack(cxs, cxs);
            unsigned long long cy = f2_pack(cys, cys);
            unsigned long long cz = f2_pack(czs, czs);
            #pragma unroll
            for (int k = 0; k < 8; k++) {
                unsigned long long dx = f2_add(NX[k], cx);
                unsigned long long dy = f2_add(NY[k], cy);
                unsigned long long dz = f2_add(NZ[k], cz);
                unsigned long long d = f2_add(f2_add(f2_mul(dx, dx), f2_mul(dy, dy)),
                                              f2_mul(dz, dz));
                float2 f = f2_unpack(d);
                dd[2 * k]     = fminf(dd[2 * k], f.x);
                dd[2 * k + 1] = fminf(dd[2 * k + 1], f.y);
            }
            // ---- local max via pure fmax tree (FMNMX lat4, depth 4 = ~16cyc) ----
            float m8[8];
            #pragma unroll
            for (int j = 0; j < 8; j++) m8[j] = fmaxf(dd[2 * j], dd[2 * j + 1]);
            float m4a = fmaxf(m8[0], m8[1]), m4b = fmaxf(m8[2], m8[3]);
            float m4c = fmaxf(m8[4], m8[5]), m4d = fmaxf(m8[6], m8[7]);
            float bv = fmaxf(fmaxf(m4a, m4b), fmaxf(m4c, m4d));
            // warp max (dists >= 0 -> float bits monotone as u32)
            unsigned vb = __float_as_uint(bv);
            unsigned wm = __reduce_max_sync(0xffffffffu, vb);
            // ---- index recovery: equality match per slot, parallel min tree ----
            int cand[16];
            #pragma unroll
            for (int k = 0; k < 8; k++) {
                cand[2 * k]     = (__float_as_uint(dd[2 * k])     == wm) ? (2 * tid + 512 * k)     : 0x7fffffff;
                cand[2 * k + 1] = (__float_as_uint(dd[2 * k + 1]) == wm) ? (2 * tid + 512 * k + 1) : 0x7fffffff;
            }
            #pragma unroll
            for (int off = 8; off; off >>= 1)
                #pragma unroll
                for (int j = 0; j < off; j++)
                    cand[j] = min(cand[j], cand[j + off]);
            unsigned wi = __reduce_min_sync(0xffffffffu, (unsigned)cand[0]);

            int p = s & 1;
            if (lane == 0) { rv[p][warp] = wm; ri[p][warp] = wi; }
            __syncthreads();
            // final reduce over 8 warp partials (all warps redundantly)
            unsigned v  = rv[p][lane & 7];
            unsigned i2 = ri[p][lane & 7];
            unsigned m2 = __reduce_max_sync(0xffffffffu, v);
            unsigned c2 = (v == m2) ? i2 : 0xffffffffu;
            far = (int)__reduce_min_sync(0xffffffffu, c2);

            if (tid == 0 && (s & 31) == 31) {
                __threadfence();
                *(volatile int*)&g_prog[b] = s + 1;
            }
        }
        return;
    }

    // ======================= WORKERS =======================
    {
        unsigned mysm;
        asm("mov.u32 %0, %%smid;" : "=r"(mysm));
        while (*(volatile int*)&g_smid_ready < 8) __nanosleep(64);
        bool onfps = false;
        #pragma unroll
        for (int i = 0; i < 8; i++) onfps |= (g_fps_sm[i] == (int)mysm);
        if (onfps) return;   // keep FPS SMs uncontended
    }

    __shared__ int s_item;
    for (;;) {
        if (tid == 0) s_item = atomicAdd(&g_q, 1);
        __syncthreads();
        int it = s_item;
        __syncthreads();
        if (it >= 640) return;

        if (it < 128) {
            // ---------- mlp1 item: conv1(3->32)+BN1 partials, 256 pts ----------
            __shared__ float sW1[96], sb1[32], ssum[32], ssq[32];
            if (tid < 96) sW1[tid] = W1[tid];
            if (tid < 32) { sb1[tid] = b1[tid]; ssum[tid] = 0.0f; ssq[tid] = 0.0f; }
            __syncthreads();
            int p = it * 256 + tid;
            float X = x[3 * p], Y = x[3 * p + 1], Z = x[3 * p + 2];
            int lane = tid & 31;
            for (int c = 0; c < 32; c++) {
                float v = fmaf(sW1[3 * c + 2], Z,
                          fmaf(sW1[3 * c + 1], Y, fmaf(sW1[3 * c], X, sb1[c])));
                g_y1[p * 32 + c] = v;
                float sv = v, sq = v * v;
                #pragma unroll
                for (int off = 16; off; off >>= 1) {
                    sv += __shfl_down_sync(0xffffffffu, sv, off);
                    sq += __shfl_down_sync(0xffffffffu, sq, off);
                }
                if (lane == 0) { atomicAdd(&ssum[c], sv); atomicAdd(&ssq[c], sq); }
            }
            __syncthreads();
            if (tid < 32) {
                g_p1[it * 64 + tid] = ssum[tid];
                g_p1[it * 64 + 32 + tid] = ssq[tid];
            }
            __threadfence();
            __syncthreads();
            if (tid == 0) atomicAdd(&g_done1, 1);
        } else if (it < 384) {
            // ---------- mlp2 item: BN1+ReLU+conv2(32->64), 128 pts, transposed ----------
            int j = it - 128;                        // 0..255 -> covers all 32768 pts
            float* y1t = (float*)smraw;              // [128*32]
            float* W2s = (float*)smraw + 4096;       // [64*36] padded
            __shared__ float sc1[32], sh1[32], sb2[64];
            if (tid == 0) { while (*(volatile int*)&g_done1 < 128) __nanosleep(64); }
            __syncthreads();
            __threadfence();
            if (tid < 32) {
                float sum = 0.0f, sq = 0.0f;
                for (int k = 0; k < 128; k++) {
                    sum += g_p1[k * 64 + tid];
                    sq  += g_p1[k * 64 + 32 + tid];
                }
                float mean = sum / 32768.0f;
                float var  = sq / 32768.0f - mean * mean;
                float scl  = g1[tid] * rsqrtf(var + 1e-5f);
                sc1[tid] = scl;
                sh1[tid] = be1[tid] - mean * scl;
            }
            if (tid < 64) sb2[tid] = b2[tid];
            for (int i = tid; i < 2048; i += 256) {
                int o = i >> 5, c = i & 31;
                W2s[o * 36 + c] = W2[i];
            }
            __syncthreads();
            int p0 = j * 128;
            for (int i = tid; i < 4096; i += 256) {
                int c = i & 31;
                y1t[i] = fmaxf(fmaf(g_y1[p0 * 32 + i], sc1[c], sh1[c]), 0.0f);
            }
            __syncthreads();
            int o = tid & 63, q = tid >> 6;
            float acc[32];
            #pragma unroll
            for (int p = 0; p < 32; p++) acc[p] = sb2[o];
            const float4* wr = (const float4*)(W2s + o * 36);
            #pragma unroll
            for (int c4 = 0; c4 < 8; c4++) {
                float4 w = wr[c4];
                #pragma unroll
                for (int p = 0; p < 32; p++) {
                    float4 v = *(const float4*)(y1t + (q * 32 + p) * 32 + c4 * 4);
                    acc[p] = fmaf(w.x, v.x, fmaf(w.y, v.y,
                             fmaf(w.z, v.z, fmaf(w.w, v.w, acc[p]))));
                }
            }
            #pragma unroll
            for (int p = 0; p < 32; p++)
                g_feats[(p0 + q * 32 + p) * 64 + o] = acc[p];
            __threadfence();
            __syncthreads();
            if (tid == 0) atomicAdd(&g_done2, 1);
        } else {
            // ---------- knn item: 64 queries, 4 threads/query ----------
            int k = it - 384;
            int b = k & 7, grp = k >> 3;
            int s0 = grp * 64;
            float* sx = (float*)smraw;           // [1056]
            float* sy = sx + 1056;
            float* sz = sy + 1056;
            float* snn = sz + 1056;
            float2* mg = (float2*)(smraw + 16896);   // [64*64]
            int* klist = (int*)(smraw + 49664);      // [64*16]

            if (tid == 0) { while (*(volatile int*)&g_prog[b] < s0 + 64) __nanosleep(128); }
            __syncthreads();
            __threadfence();

            int r = tid & 3, ql = tid >> 2;
            int s = s0 + ql;
            const float* xb = x + b * 12288;
            int qi = g_fps[b * 2048 + s];
            float qx = xb[3 * qi], qy = xb[3 * qi + 1], qz = xb[3 * qi + 2];
            float qn = __fadd_rn(__fadd_rn(__fmul_rn(qx, qx), __fmul_rn(qy, qy)),
                                 __fmul_rn(qz, qz));
            unsigned long long qx2 = f2_pack(qx, qx), qy2 = f2_pack(qy, qy);
            unsigned long long qz2 = f2_pack(qz, qz);
            unsigned long long qn2 = f2_pack(qn, qn), n2 = f2_pack(-2.0f, -2.0f);

            float bd[16];
            int   bi[16];
            #pragma unroll
            for (int m = 0; m < 16; m++) { bd[m] = FLTMAX; bi[m] = 0x7fffffff; }
            float w = FLTMAX;
            int ws = 0;

            for (int t = 0; t < 4; t++) {
                __syncthreads();
                for (int jj = tid; jj < 1024; jj += 256) {
                    int i = t * 1024 + jj;
                    int slotp = (jj >> 8) * 264 + (jj & 255);
                    float X = xb[3 * i], Y = xb[3 * i + 1], Z = xb[3 * i + 2];
                    sx[slotp] = X; sy[slotp] = Y; sz[slotp] = Z;
                    snn[slotp] = __fadd_rn(__fadd_rn(__fmul_rn(X, X), __fmul_rn(Y, Y)),
                                           __fmul_rn(Z, Z));
                }
                __syncthreads();
                int qbase = r * 264;
                const float2* px2 = (const float2*)(sx + qbase);
                const float2* py2 = (const float2*)(sy + qbase);
                const float2* pz2 = (const float2*)(sz + qbase);
                const float2* pn2 = (const float2*)(snn + qbase);
                int base = t * 1024 + r * 256;
                for (int j2 = 0; j2 < 128; j2++) {
                    float2 vx = px2[j2], vy = py2[j2], vz = pz2[j2], vn = pn2[j2];
                    unsigned long long dot = f2_add(f2_add(f2_mul(qx2, f2_pack(vx.x, vx.y)),
                                                           f2_mul(qy2, f2_pack(vy.x, vy.y))),
                                                    f2_mul(qz2, f2_pack(vz.x, vz.y)));
                    unsigned long long d2 = f2_add(f2_add(qn2, f2_pack(vn.x, vn.y)),
                                                   f2_mul(dot, n2));
                    float2 d = f2_unpack(d2);
                    if (fminf(d.x, d.y) < w) {
                        #pragma unroll
                        for (int h = 0; h < 2; h++) {
                            float dv = h ? d.y : d.x;
                            if (dv < w) {
                                int i = base + 2 * j2 + h;
                                #pragma unroll
                                for (int m = 0; m < 16; m++)
                                    if (m == ws) { bd[m] = dv; bi[m] = i; }
                                float nw = -FLTMAX; int nwi = -1; int nws = 0;
                                #pragma unroll
                                for (int m = 0; m < 16; m++) {
                                    bool better = (bd[m] > nw) || (bd[m] == nw && bi[m] > nwi);
                                    if (better) { nw = bd[m]; nwi = bi[m]; nws = m; }
                                }
                                w = nw; ws = nws;
                            }
                        }
                    }
                }
            }

            // 4-way rank merge over disjoint-index union of 64 candidates
            __syncthreads();
            #pragma unroll
            for (int m = 0; m < 16; m++)
                mg[ql * 64 + r * 16 + m] = make_float2(bd[m], __int_as_float(bi[m]));
            __syncwarp();
            int rank[16];
            #pragma unroll
            for (int m = 0; m < 16; m++) rank[m] = 0;
            const float2* u = &mg[ql * 64];
            for (int e = 0; e < 64; e++) {
                float2 pe = u[e];
                int pi = __float_as_int(pe.y);
                #pragma unroll
                for (int m = 0; m < 16; m++)
                    rank[m] += (pe.x < bd[m]) || (pe.x == bd[m] && pi < bi[m]);
            }
            int* kl = &klist[ql * 16];
            #pragma unroll
            for (int m = 0; m < 16; m++)
                if (rank[m] < 16) kl[rank[m]] = bi[m];
            __syncwarp();

            int idx16[16];
            #pragma unroll
            for (int kk = 0; kk < 16; kk++) idx16[kk] = kl[kk];

            // wait for all feats before gather
            __syncthreads();
            if (tid == 0) { while (*(volatile int*)&g_done2 < 256) __nanosleep(128); }
            __syncthreads();
            __threadfence();

            float* op = g_pooled + (b * 2048 + s) * 68;
            if (r == 0) {
                float mx = -FLTMAX, my = -FLTMAX, mz = -FLTMAX;
                #pragma unroll
                for (int kk = 0; kk < 16; kk++) {
                    int i = idx16[kk];
                    mx = fmaxf(mx, __fsub_rn(xb[3 * i], qx));
                    my = fmaxf(my, __fsub_rn(xb[3 * i + 1], qy));
                    mz = fmaxf(mz, __fsub_rn(xb[3 * i + 2], qz));
                }
                op[64] = mx; op[65] = my; op[66] = mz; op[67] = 0.0f;
            }
            const float* fb = g_feats + b * 4096 * 64 + r * 16;
            float4 acc[4];
            #pragma unroll
            for (int q = 0; q < 4; q++)
                acc[q] = make_float4(-FLTMAX, -FLTMAX, -FLTMAX, -FLTMAX);
            #pragma unroll
            for (int kk = 0; kk < 16; kk++) {
                const float4* fr = (const float4*)(fb + idx16[kk] * 64);
                #pragma unroll
                for (int q = 0; q < 4; q++) {
                    float4 f = fr[q];
                    acc[q].x = fmaxf(acc[q].x, f.x);
                    acc[q].y = fmaxf(acc[q].y, f.y);
                    acc[q].z = fmaxf(acc[q].z, f.z);
                    acc[q].w = fmaxf(acc[q].w, f.w);
                }
            }
            float4* of = (float4*)(op + r * 16);
            #pragma unroll
            for (int q = 0; q < 4; q++) of[q] = acc[q];
            __syncthreads();
        }
    }
}

// ---------------- mlp3: conv3(67->64) transposed + BN2 partials ----------------
__global__ void __launch_bounds__(128) mlp3_kernel(const float* __restrict__ W3,
                                                   const float* __restrict__ b3) {
    __shared__ float P[64 * 68];
    __shared__ float W[64 * 68];
    __shared__ float sb[64];
    __shared__ float red[128];
    int tid = threadIdx.x;
    for (int i = tid; i < 64 * 68; i += 128) {
        int o = i / 68, c = i - o * 68;
        W[i] = (c < 64) ? W3[o * 67 + 3 + c] : ((c < 67) ? W3[o * 67 + (c - 64)] : 0.0f);
    }
    if (tid < 64) sb[tid] = b3[tid];
    int p0 = blockIdx.x * 64;
    for (int i = tid; i < 64 * 68; i += 128) P[i] = g_pooled[p0 * 68 + i];
    __syncthreads();
    int o = tid & 63, h = tid >> 6;
    float acc[32];
    #pragma unroll
    for (int p = 0; p < 32; p++) acc[p] = sb[o];
    const float4* wr = (const float4*)(W + o * 68);
    #pragma unroll
    for (int c4 = 0; c4 < 17; c4++) {
        float4 w = wr[c4];
        #pragma unroll
        for (int p = 0; p < 32; p++) {
            float4 v = *(const float4*)(P + (h * 32 + p) * 68 + c4 * 4);
            acc[p] = fmaf(w.x, v.x, fmaf(w.y, v.y, fmaf(w.z, v.z, fmaf(w.w, v.w, acc[p]))));
        }
    }
    float ssum = 0.0f, ssq = 0.0f;
    #pragma unroll
    for (int p = 0; p < 32; p++) {
        g_y3[(p0 + h * 32 + p) * 64 + o] = acc[p];
        ssum += acc[p]; ssq += acc[p] * acc[p];
    }
    red[tid] = ssum;
    __syncthreads();
    if (tid < 64) g_p2[blockIdx.x * 128 + tid] = red[tid] + red[tid + 64];
    __syncthreads();
    red[tid] = ssq;
    __syncthreads();
    if (tid < 64) g_p2[blockIdx.x * 128 + 64 + tid] = red[tid] + red[tid + 64];
}

// ---------------- mlp4: BN2 finalize (in-block) + ReLU + conv4 -> out ----------------
__global__ void __launch_bounds__(128) mlp4_kernel(const float* __restrict__ W4,
                                                   const float* __restrict__ b4,
                                                   const float* __restrict__ g2,
                                                   const float* __restrict__ be2,
                                                   float* __restrict__ out) {
    __shared__ float Y[64 * 64];
    __shared__ float W[64 * 68];
    __shared__ float sb[64], sc[64], sh[64];
    int tid = threadIdx.x;
    if (tid < 64) {
        sb[tid] = b4[tid];
        float sum = 0.0f, sq = 0.0f;
        for (int k = 0; k < 256; k++) {
            sum += g_p2[k * 128 + tid];
            sq  += g_p2[k * 128 + 64 + tid];
        }
        float mean = sum / 16384.0f;
        float var  = sq / 16384.0f - mean * mean;
        float scl  = g2[tid] * rsqrtf(var + 1e-5f);
        sc[tid] = scl;
        sh[tid] = be2[tid] - mean * scl;
    }
    for (int i = tid; i < 64 * 68; i += 128) {
        int o = i / 68, c = i - o * 68;
        W[i] = (c < 64) ? W4[o * 64 + c] : 0.0f;
    }
    __syncthreads();
    int p0 = blockIdx.x * 64;
    for (int i = tid; i < 4096; i += 128) {
        int c = i & 63;
        Y[i] = fmaxf(fmaf(g_y3[p0 * 64 + i], sc[c], sh[c]), 0.0f);
    }
    __syncthreads();
    int o = tid & 63, h = tid >> 6;
    float acc[32];
    #pragma unroll
    for (int p = 0; p < 32; p++) acc[p] = sb[o];
    const float4* wr = (const float4*)(W + o * 68);
    #pragma unroll
    for (int c4 = 0; c4 < 16; c4++) {
        float4 w = wr[c4];
        #pragma unroll
        for (int p = 0; p < 32; p++) {
            float4 v = *(const float4*)(Y + (h * 32 + p) * 64 + c4 * 4);
            acc[p] = fmaf(w.x, v.x, fmaf(w.y, v.y, fmaf(w.z, v.z, fmaf(w.w, v.w, acc[p]))));
        }
    }
    #pragma unroll
    for (int p = 0; p < 32; p++)
        out[(p0 + h * 32 + p) * 64 + o] = acc[p];
}

// ---------------- launch ----------------
extern "C" void kernel_launch(void* const* d_in, const int* in_sizes, int n_in,
                              void* d_out, int out_size) {
    const float* x   = (const float*)d_in[0];
    const float* W1  = (const float*)d_in[1];
    const float* b1  = (const float*)d_in[2];
    const float* g1  = (const float*)d_in[3];
    const float* be1 = (const float*)d_in[4];
    const float* W2  = (const float*)d_in[5];
    const float* b2  = (const float*)d_in[6];
    const float* W3  = (const float*)d_in[7];
    const float* b3  = (const float*)d_in[8];
    const float* g2  = (const float*)d_in[9];
    const float* be2 = (const float*)d_in[10];
    const float* W4  = (const float*)d_in[11];
    const float* b4  = (const float*)d_in[12];
    float* out = (float*)d_out;

    cudaFuncSetAttribute(mega_kernel, cudaFuncAttributeMaxDynamicSharedMemorySize, 53760);

    init_kernel<<<1, 32>>>();
    mega_kernel<<<296, 256, 53760>>>(x, W1, b1, W2, b2, g1, be1);
    mlp3_kernel<<<256, 128>>>(W3, b3);
    mlp4_kernel<<<256, 128>>>(W4, b4, g2, be2, out);
}